// round 4
// baseline (speedup 1.0000x reference)
#include <cuda_runtime.h>

#define NN 50000
#define EE 800000
#define DD 128

// ---------------- scratch (__device__ globals; no runtime allocation) ------
__device__ float g_q[NN * DD];
__device__ float g_k[NN * DD];
__device__ float g_v[NN * DD];
__device__ float g_h[NN * DD];
__device__ int   g_cnt[NN];
__device__ int   g_off[NN + 1];
__device__ int   g_csrc[EE];
__device__ int   g_stride;     // 1 = int32 indices, 2 = int64 (read low word)

// ---------------- dtype sniffer -------------------------------------------
__global__ void sniff_kernel(const int* __restrict__ dstw)
{
    __shared__ int any_nonzero;
    if (threadIdx.x == 0) any_nonzero = 0;
    __syncthreads();
    int v = dstw[2 * threadIdx.x + 1];   // odd words of first 512 pairs
    if (v != 0) atomicOr(&any_nonzero, 1);
    __syncthreads();
    if (threadIdx.x == 0) g_stride = any_nonzero ? 1 : 2;
}

// ---------------- GEMM core: 128x128 tile, 8x8 micro-tile ------------------
// Xs transposed (Xs[k][row], stride 132 for alignment + bank spread).
// Per k: 4 LDS.128 + 64 FFMA -> 94% FFMA issue fraction.
__device__ __forceinline__ void gemm_core(const float* __restrict__ Xin,
                                          const float* __restrict__ W,
                                          const float* __restrict__ b,
                                          float* __restrict__ C)
{
    __shared__ float Xs[32][132];    // ~16.5 KB
    __shared__ float Ws[32][128];    // 16 KB

    const int tid  = threadIdx.x;        // 0..255
    const int row0 = blockIdx.x * 128;
    const int tx   = tid & 15;           // col group
    const int ty   = tid >> 4;           // row group

    float acc[8][8];
#pragma unroll
    for (int i = 0; i < 8; i++)
#pragma unroll
        for (int j = 0; j < 8; j++) acc[i][j] = 0.f;

#pragma unroll
    for (int kc = 0; kc < 4; kc++) {
        // X chunk: rows row0..+127, k = kc*32..+31, transposed into Xs
#pragma unroll
        for (int it = 0; it < 4; it++) {
            int i  = tid + it * 256;     // 0..1023
            int r  = i >> 3;             // 0..127
            int kq = i & 7;              // float4 index in k
            int gr = row0 + r;
            float4 vx = make_float4(0.f, 0.f, 0.f, 0.f);
            if (gr < NN) vx = *(const float4*)&Xin[gr * DD + kc * 32 + kq * 4];
            Xs[kq * 4 + 0][r] = vx.x;
            Xs[kq * 4 + 1][r] = vx.y;
            Xs[kq * 4 + 2][r] = vx.z;
            Xs[kq * 4 + 3][r] = vx.w;
        }
        // W chunk: Ws[k][c]
#pragma unroll
        for (int it = 0; it < 4; it++) {
            int i  = tid + it * 256;
            int r  = i >> 5;             // k 0..31
            int c4 = i & 31;
            *(float4*)&Ws[r][c4 * 4] =
                *(const float4*)&W[(kc * 32 + r) * DD + c4 * 4];
        }
        __syncthreads();

#pragma unroll
        for (int k = 0; k < 32; k++) {
            float4 a0 = *(float4*)&Xs[k][ty * 4];
            float4 a1 = *(float4*)&Xs[k][ty * 4 + 64];
            float4 b0 = *(float4*)&Ws[k][tx * 4];
            float4 b1 = *(float4*)&Ws[k][tx * 4 + 64];
            float av[8] = {a0.x, a0.y, a0.z, a0.w, a1.x, a1.y, a1.z, a1.w};
            float bv[8] = {b0.x, b0.y, b0.z, b0.w, b1.x, b1.y, b1.z, b1.w};
#pragma unroll
            for (int i = 0; i < 8; i++)
#pragma unroll
                for (int j = 0; j < 8; j++)
                    acc[i][j] += av[i] * bv[j];
        }
        __syncthreads();
    }

    const float4 bb0 = *(const float4*)&b[tx * 4];
    const float4 bb1 = *(const float4*)&b[tx * 4 + 64];
#pragma unroll
    for (int i = 0; i < 8; i++) {
        int gr = row0 + ty * 4 + (i & 3) + ((i >> 2) << 6);
        if (gr < NN) {
            float4 o0 = make_float4(acc[i][0] + bb0.x, acc[i][1] + bb0.y,
                                    acc[i][2] + bb0.z, acc[i][3] + bb0.w);
            float4 o1 = make_float4(acc[i][4] + bb1.x, acc[i][5] + bb1.y,
                                    acc[i][6] + bb1.z, acc[i][7] + bb1.w);
            *(float4*)&C[gr * DD + tx * 4]      = o0;
            *(float4*)&C[gr * DD + tx * 4 + 64] = o1;
        }
    }
}

// fused Q/K/V projections: blockIdx.y selects matrix
__global__ __launch_bounds__(256, 2)
void qkv_kernel(const float* __restrict__ x,
                const float* __restrict__ Wq, const float* __restrict__ bq,
                const float* __restrict__ Wk, const float* __restrict__ bk,
                const float* __restrict__ Wv, const float* __restrict__ bv)
{
    const float* W;
    const float* b;
    float*       C;
    if (blockIdx.y == 0)      { W = Wq; b = bq; C = g_q; }
    else if (blockIdx.y == 1) { W = Wk; b = bk; C = g_k; }
    else                      { W = Wv; b = bv; C = g_v; }
    gemm_core(x, W, b, C);
}

// output projection: reads g_h, writes d_out
__global__ __launch_bounds__(256, 2)
void out_kernel(const float* __restrict__ Wo, const float* __restrict__ bo,
                float* __restrict__ out)
{
    gemm_core(g_h, Wo, bo, out);
}

// ---------------- CSR build ------------------------------------------------
__global__ void zero_cnt_kernel()
{
    int i = blockIdx.x * blockDim.x + threadIdx.x;
    if (i < NN) g_cnt[i] = 0;
}

__global__ void hist_kernel(const int* __restrict__ dstw)
{
    int e = blockIdx.x * blockDim.x + threadIdx.x;
    if (e < EE) {
        int d = dstw[e * g_stride];
        atomicAdd(&g_cnt[d], 1);
    }
}

// segment-scan: thread-sequential partials + one block scan + add-back
__global__ void scan_kernel()
{
    __shared__ int sh[1024];
    const int SEG = (NN + 1023) / 1024;      // 49
    int t   = threadIdx.x;
    int beg = t * SEG;
    int end = min(beg + SEG, NN);

    int sum = 0;
    for (int i = beg; i < end; i++) sum += g_cnt[i];
    sh[t] = sum;
    __syncthreads();
    for (int o = 1; o < 1024; o <<= 1) {
        int v = (t >= o) ? sh[t - o] : 0;
        __syncthreads();
        sh[t] += v;
        __syncthreads();
    }
    int run = (t == 0) ? 0 : sh[t - 1];
    for (int i = beg; i < end; i++) {
        run += g_cnt[i];
        g_off[i + 1] = run;
    }
    if (t == 0) g_off[0] = 0;
}

__global__ void scatter_kernel(const int* __restrict__ srcw,
                               const int* __restrict__ dstw)
{
    int e = blockIdx.x * blockDim.x + threadIdx.x;
    if (e < EE) {
        int st  = g_stride;
        int d   = dstw[e * st];
        int s   = srcw[e * st];
        int pos = atomicAdd(&g_cnt[d], 1);
        g_csrc[g_off[d] + pos] = s;
    }
}

// ---------------- aggregation: warp per destination node -------------------
__global__ void agg_kernel()
{
    int w    = (blockIdx.x * blockDim.x + threadIdx.x) >> 5;
    int lane = threadIdx.x & 31;
    if (w >= NN) return;

    const float4 q4 = *(const float4*)&g_q[w * DD + lane * 4];
    const float qx = q4.x * 0.25f;   // fold 1/sqrt(d_k)=0.25 into q
    const float qy = q4.y * 0.25f;
    const float qz = q4.z * 0.25f;
    const float qw = q4.w * 0.25f;

    float zx = 0.f, zy = 0.f, zz = 0.f, zw = 0.f;
    float ax = 0.f, ay = 0.f, az = 0.f, aw = 0.f;

    const int beg = g_off[w];
    const int end = g_off[w + 1];

    for (int j0 = beg; j0 < end; j0 += 32) {
        int myS = (j0 + lane < end) ? g_csrc[j0 + lane] : 0;
        int cnt = min(32, end - j0);
        for (int t = 0; t < cnt; t++) {
            int s = __shfl_sync(0xffffffffu, myS, t);
            const float4 kk = *(const float4*)&g_k[s * DD + lane * 4];
            const float4 vv = *(const float4*)&g_v[s * DD + lane * 4];
            float mx = __expf(kk.x * qx);
            float my = __expf(kk.y * qy);
            float mz = __expf(kk.z * qz);
            float mw = __expf(kk.w * qw);
            zx += mx; zy += my; zz += mz; zw += mw;
            ax += mx * vv.x;
            ay += my * vv.y;
            az += mz * vv.z;
            aw += mw * vv.w;
        }
    }

    float4 o = make_float4(ax / zx, ay / zy, az / zz, aw / zw);
    *(float4*)&g_h[w * DD + lane * 4] = o;
}

// ---------------- launch ---------------------------------------------------
extern "C" void kernel_launch(void* const* d_in, const int* in_sizes, int n_in,
                              void* d_out, int out_size)
{
    const float* x   = (const float*)d_in[0];
    const int*   src = (const int*)d_in[1];   // int32 or int64 words; sniffed
    const int*   dst = (const int*)d_in[2];
    const float* Wq  = (const float*)d_in[3];
    const float* bq  = (const float*)d_in[4];
    const float* Wk  = (const float*)d_in[5];
    const float* bk  = (const float*)d_in[6];
    const float* Wv  = (const float*)d_in[7];
    const float* bv  = (const float*)d_in[8];
    const float* Wo  = (const float*)d_in[9];
    const float* bo  = (const float*)d_in[10];
    float*       out = (float*)d_out;

    const int gemm_blocks = (NN + 127) / 128;      // 391
    const int zero_blocks = (NN + 255) / 256;      // 196
    const int edge_blocks = (EE + 255) / 256;      // 3125
    const int agg_blocks  = (NN * 32 + 255) / 256; // 6250

    // detect index dtype (int32 vs int64)
    sniff_kernel<<<1, 512>>>(dst);

    // CSR by dst (independent of projections)
    zero_cnt_kernel<<<zero_blocks, 256>>>();
    hist_kernel<<<edge_blocks, 256>>>(dst);
    scan_kernel<<<1, 1024>>>();
    zero_cnt_kernel<<<zero_blocks, 256>>>();
    scatter_kernel<<<edge_blocks, 256>>>(src, dst);

    // fused Q/K/V projections
    qkv_kernel<<<dim3(gemm_blocks, 3), 256>>>(x, Wq, bq, Wk, bk, Wv, bv);

    // edge softmax-aggregate
    agg_kernel<<<agg_blocks, 256>>>();

    // output projection
    out_kernel<<<gemm_blocks, 256>>>(Wo, bo, out);
}

// round 5
// speedup vs baseline: 1.1577x; 1.1577x over previous
#include <cuda_runtime.h>

#define NN 50000
#define EE 800000
#define DD 128

// ---------------- scratch (__device__ globals; no runtime allocation) ------
__device__ float g_q[NN * DD];
__device__ float g_k[NN * DD];
__device__ float g_v[NN * DD];
__device__ float g_h[NN * DD];
__device__ int   g_cnt[NN];      // zero-initialized; scatter restores zeros
__device__ int   g_off[NN + 1];
__device__ int   g_csrc[EE];
__device__ int   g_part[64];
__device__ int   g_pofs[64];
__device__ int   g_stride;       // 1 = int32 indices, 2 = int64 (low word)

// ---------------- dtype sniffer -------------------------------------------
__global__ void sniff_kernel(const int* __restrict__ dstw)
{
    __shared__ int any_nonzero;
    if (threadIdx.x == 0) any_nonzero = 0;
    __syncthreads();
    int v = dstw[2 * threadIdx.x + 1];   // odd words of first 512 pairs
    if (v != 0) atomicOr(&any_nonzero, 1);
    __syncthreads();
    if (threadIdx.x == 0) g_stride = any_nonzero ? 1 : 2;
}

// ---------------- GEMM core (R3-proven): 64x128 tile, 8x4 micro-tile -------
template <int SEL>
__device__ __forceinline__ void gemm_core(const float* __restrict__ X,
                                          const float* __restrict__ W,
                                          const float* __restrict__ b,
                                          float* __restrict__ Cout)
{
    __shared__ float Xs[64 * 64];    // 16 KB
    __shared__ float Ws[64 * 128];   // 32 KB

    float* C;
    if      (SEL == 0) C = g_q;
    else if (SEL == 1) C = g_k;
    else if (SEL == 2) C = g_v;
    else               C = Cout;

    const float* Xin = (SEL == 3) ? g_h : X;

    const int tid  = threadIdx.x;       // 0..255
    const int row0 = blockIdx.x * 64;

    const int tx = tid & 31;   // col group (float4)
    const int ty = tid >> 5;   // row group (0..7)
    const int c0 = tx * 4;
    const int r0 = ty * 8;

    float acc[8][4];
#pragma unroll
    for (int i = 0; i < 8; i++)
#pragma unroll
        for (int j = 0; j < 4; j++) acc[i][j] = 0.f;

#pragma unroll
    for (int kk = 0; kk < 2; kk++) {
        for (int i = tid; i < 64 * 16; i += 256) {
            int r  = i >> 4;
            int c4 = i & 15;
            int gr = row0 + r;
            float4 vx = make_float4(0.f, 0.f, 0.f, 0.f);
            if (gr < NN) vx = *(const float4*)&Xin[gr * DD + kk * 64 + c4 * 4];
            *(float4*)&Xs[r * 64 + c4 * 4] = vx;
        }
        for (int i = tid; i < 64 * 32; i += 256) {
            int r  = i >> 5;
            int c4 = i & 31;
            *(float4*)&Ws[r * DD + c4 * 4] =
                *(const float4*)&W[(kk * 64 + r) * DD + c4 * 4];
        }
        __syncthreads();

#pragma unroll 8
        for (int k = 0; k < 64; k++) {
            float4 wv = *(float4*)&Ws[k * DD + c0];
            float xv[8];
#pragma unroll
            for (int i = 0; i < 8; i++) xv[i] = Xs[(r0 + i) * 64 + k];
#pragma unroll
            for (int i = 0; i < 8; i++) {
                acc[i][0] += xv[i] * wv.x;
                acc[i][1] += xv[i] * wv.y;
                acc[i][2] += xv[i] * wv.z;
                acc[i][3] += xv[i] * wv.w;
            }
        }
        __syncthreads();
    }

    const float4 bv = *(const float4*)&b[c0];
#pragma unroll
    for (int i = 0; i < 8; i++) {
        int gr = row0 + r0 + i;
        if (gr < NN) {
            float4 o = make_float4(acc[i][0] + bv.x, acc[i][1] + bv.y,
                                   acc[i][2] + bv.z, acc[i][3] + bv.w);
            *(float4*)&C[gr * DD + c0] = o;
        }
    }
}

// fused Q/K/V projections: blockIdx.y selects matrix
__global__ void qkv_kernel(const float* __restrict__ x,
                           const float* __restrict__ Wq, const float* __restrict__ bq,
                           const float* __restrict__ Wk, const float* __restrict__ bk,
                           const float* __restrict__ Wv, const float* __restrict__ bv)
{
    if (blockIdx.y == 0)      gemm_core<0>(x, Wq, bq, nullptr);
    else if (blockIdx.y == 1) gemm_core<1>(x, Wk, bk, nullptr);
    else                      gemm_core<2>(x, Wv, bv, nullptr);
}

__global__ void out_kernel(const float* __restrict__ Wo,
                           const float* __restrict__ bo,
                           float* __restrict__ out)
{
    gemm_core<3>(nullptr, Wo, bo, out);
}

// ---------------- CSR build ------------------------------------------------
__global__ void zero_cnt_kernel()
{
    int i = blockIdx.x * blockDim.x + threadIdx.x;
    if (i < NN) g_cnt[i] = 0;
}

__global__ void hist_kernel(const int* __restrict__ dstw)
{
    int e = blockIdx.x * blockDim.x + threadIdx.x;
    if (e < EE) {
        int d = dstw[e * g_stride];
        atomicAdd(&g_cnt[d], 1);
    }
}

// ---- hierarchical scan: 49-blk partials -> 64-thr mid scan -> 49-blk final
#define SCAN_NB 49

__global__ void scan_part_kernel()   // 49 blocks x 256 thr
{
    __shared__ int warpsum[8];
    int base = blockIdx.x * 1024 + threadIdx.x * 4;
    int s = 0;
#pragma unroll
    for (int j = 0; j < 4; j++) {
        int i = base + j;
        if (i < NN) s += g_cnt[i];
    }
    for (int o = 16; o > 0; o >>= 1) s += __shfl_down_sync(0xffffffffu, s, o);
    if ((threadIdx.x & 31) == 0) warpsum[threadIdx.x >> 5] = s;
    __syncthreads();
    if (threadIdx.x < 8) {
        int v = warpsum[threadIdx.x];
        for (int o = 4; o > 0; o >>= 1) v += __shfl_down_sync(0xffu, v, o);
        if (threadIdx.x == 0) g_part[blockIdx.x] = v;
    }
}

__global__ void scan_mid_kernel()    // 1 block x 64 thr
{
    __shared__ int sh[64];
    int t = threadIdx.x;
    int v = (t < SCAN_NB) ? g_part[t] : 0;
    sh[t] = v;
    __syncthreads();
    for (int o = 1; o < 64; o <<= 1) {
        int u = (t >= o) ? sh[t - o] : 0;
        __syncthreads();
        sh[t] += u;
        __syncthreads();
    }
    if (t < SCAN_NB) g_pofs[t] = (t == 0) ? 0 : sh[t - 1];
}

__global__ void scan_final_kernel()  // 49 blocks x 256 thr
{
    __shared__ int wpref[8];
    int t = threadIdx.x, lane = t & 31, w = t >> 5;
    int base = blockIdx.x * 1024 + t * 4;
    int c[4];
    int s = 0;
#pragma unroll
    for (int j = 0; j < 4; j++) {
        int i = base + j;
        c[j] = (i < NN) ? g_cnt[i] : 0;
        s += c[j];
    }
    int inc = s;
    for (int o = 1; o < 32; o <<= 1) {
        int u = __shfl_up_sync(0xffffffffu, inc, o);
        if (lane >= o) inc += u;
    }
    if (lane == 31) wpref[w] = inc;
    __syncthreads();
    if (t < 8) {
        int v = wpref[t];
        for (int o = 1; o < 8; o <<= 1) {
            int u = __shfl_up_sync(0xffu, v, o);
            if (t >= o) v += u;
        }
        wpref[t] = v;
    }
    __syncthreads();
    int run = inc - s + (w ? wpref[w - 1] : 0) + g_pofs[blockIdx.x];
#pragma unroll
    for (int j = 0; j < 4; j++) {
        int i = base + j;
        run += c[j];
        if (i < NN) g_off[i + 1] = run;
    }
    if (blockIdx.x == 0 && t == 0) g_off[0] = 0;
}

// scatter with decrementing cursor: leaves g_cnt back at zero
__global__ void scatter_kernel(const int* __restrict__ srcw,
                               const int* __restrict__ dstw)
{
    int e = blockIdx.x * blockDim.x + threadIdx.x;
    if (e < EE) {
        int st  = g_stride;
        int d   = dstw[e * st];
        int s   = srcw[e * st];
        int pos = atomicSub(&g_cnt[d], 1);
        g_csrc[g_off[d] + pos - 1] = s;
    }
}

// ---------------- aggregation: warp per destination node -------------------
__global__ void agg_kernel()
{
    int w    = (blockIdx.x * blockDim.x + threadIdx.x) >> 5;
    int lane = threadIdx.x & 31;
    if (w >= NN) return;

    const float4 q4 = *(const float4*)&g_q[w * DD + lane * 4];
    const float qx = q4.x * 0.25f;   // fold 1/sqrt(d_k)=0.25 into q
    const float qy = q4.y * 0.25f;
    const float qz = q4.z * 0.25f;
    const float qw = q4.w * 0.25f;

    float zx = 0.f, zy = 0.f, zz = 0.f, zw = 0.f;
    float ax = 0.f, ay = 0.f, az = 0.f, aw = 0.f;

    const int beg = g_off[w];
    const int end = g_off[w + 1];

    for (int j0 = beg; j0 < end; j0 += 32) {
        int myS = (j0 + lane < end) ? g_csrc[j0 + lane] : 0;
        int cnt = min(32, end - j0);
        for (int t = 0; t < cnt; t++) {
            int s = __shfl_sync(0xffffffffu, myS, t);
            const float4 kk = *(const float4*)&g_k[s * DD + lane * 4];
            const float4 vv = *(const float4*)&g_v[s * DD + lane * 4];
            float mx = __expf(kk.x * qx);
            float my = __expf(kk.y * qy);
            float mz = __expf(kk.z * qz);
            float mw = __expf(kk.w * qw);
            zx += mx; zy += my; zz += mz; zw += mw;
            ax += mx * vv.x;
            ay += my * vv.y;
            az += mz * vv.z;
            aw += mw * vv.w;
        }
    }

    float4 o = make_float4(ax / zx, ay / zy, az / zz, aw / zw);
    *(float4*)&g_h[w * DD + lane * 4] = o;
}

// ---------------- launch ---------------------------------------------------
extern "C" void kernel_launch(void* const* d_in, const int* in_sizes, int n_in,
                              void* d_out, int out_size)
{
    const float* x   = (const float*)d_in[0];
    const int*   src = (const int*)d_in[1];   // int32 or int64 words; sniffed
    const int*   dst = (const int*)d_in[2];
    const float* Wq  = (const float*)d_in[3];
    const float* bq  = (const float*)d_in[4];
    const float* Wk  = (const float*)d_in[5];
    const float* bk  = (const float*)d_in[6];
    const float* Wv  = (const float*)d_in[7];
    const float* bv  = (const float*)d_in[8];
    const float* Wo  = (const float*)d_in[9];
    const float* bo  = (const float*)d_in[10];
    float*       out = (float*)d_out;

    const int gemm_blocks = (NN + 63) / 64;        // 782
    const int zero_blocks = (NN + 255) / 256;      // 196
    const int edge_blocks = (EE + 255) / 256;      // 3125
    const int agg_blocks  = (NN * 32 + 255) / 256; // 6250

    // detect index dtype (int32 vs int64)
    sniff_kernel<<<1, 512>>>(dst);

    // CSR by dst
    zero_cnt_kernel<<<zero_blocks, 256>>>();       // insurance (normally no-op)
    hist_kernel<<<edge_blocks, 256>>>(dst);
    scan_part_kernel<<<SCAN_NB, 256>>>();
    scan_mid_kernel<<<1, 64>>>();
    scan_final_kernel<<<SCAN_NB, 256>>>();
    scatter_kernel<<<edge_blocks, 256>>>(src, dst);

    // fused Q/K/V projections
    qkv_kernel<<<dim3(gemm_blocks, 3), 256>>>(x, Wq, bq, Wk, bk, Wv, bv);

    // edge softmax-aggregate
    agg_kernel<<<agg_blocks, 256>>>();

    // output projection
    out_kernel<<<gemm_blocks, 256>>>(Wo, bo, out);
}